// round 1
// baseline (speedup 1.0000x reference)
#include <cuda_runtime.h>
#include <math.h>

#define B 4
#define T 128
#define NTOK 196
#define D 768
#define KF 16
#define KT 49
#define NF (B*KF)   // 64 selected frames

// ---- output layout (float32, concatenated flat) ----
#define Z_N       (B*KF*KT*D)                 // 2,408,448
#define FIDX_OFF  ((size_t)Z_N)               // 64 entries
#define TIDX_OFF  (FIDX_OFF + B*KF)           // 3136 entries
#define FMASK_OFF (TIDX_OFF + NF*KT)          // 512 entries
#define TMASK_OFF (FMASK_OFF + B*T)           // 100,352 entries
#define TOTAL_OUT (TMASK_OFF + (size_t)B*T*NTOK)  // 2,512,512

// ---- device scratch (no allocation allowed) ----
__device__ float g_frame_repr[B*T*D];          // 1.5 MB
__device__ int   g_frame_idx[B*KF];
__device__ int   g_token_idx[NF*KT];
__device__ float g_G[(size_t)NF*NTOK*NTOK];    // 9.8 MB

// ================= block argmax (256 threads, 8 warps) =================
// strict-greater wins; ties -> lowest index (matches jnp.argmax)
__device__ __forceinline__ int block_argmax_256(float v, int ix,
                                                float* s_rv, int* s_ri, int* s_res) {
    int lane = threadIdx.x & 31, w = threadIdx.x >> 5;
#pragma unroll
    for (int o = 16; o; o >>= 1) {
        float ov = __shfl_down_sync(0xffffffffu, v, o);
        int   oi = __shfl_down_sync(0xffffffffu, ix, o);
        if (ov > v || (ov == v && oi < ix)) { v = ov; ix = oi; }
    }
    if (lane == 0) { s_rv[w] = v; s_ri[w] = ix; }
    __syncthreads();
    if (threadIdx.x == 0) {
        float bv = s_rv[0]; int bi = s_ri[0];
#pragma unroll
        for (int i = 1; i < 8; i++)
            if (s_rv[i] > bv || (s_rv[i] == bv && s_ri[i] < bi)) { bv = s_rv[i]; bi = s_ri[i]; }
        *s_res = bi;
    }
    __syncthreads();
    return *s_res;
}

// ================= K1: masked-mean frame representation =================
__global__ void frame_repr_kernel(const float* __restrict__ x,
                                  const float* __restrict__ mask) {
    int bt = blockIdx.x;                 // 0..B*T-1
    const float* xp = x + (size_t)bt * NTOK * D;
    const float* mp = mask + (size_t)bt * NTOK;
    __shared__ float sm[NTOK];
    __shared__ float s_denom;
    int tid = threadIdx.x;
    if (tid < NTOK) sm[tid] = mp[tid];
    __syncthreads();
    if (tid == 0) {
        float s = 0.f;
        for (int n = 0; n < NTOK; n++) s += sm[n];
        s_denom = fmaxf(s, 1e-6f);
    }
    __syncthreads();
    float den = s_denom;
    float a0 = 0.f, a1 = 0.f, a2 = 0.f;
#pragma unroll 4
    for (int n = 0; n < NTOK; n++) {
        float m = sm[n];
        const float* row = xp + (size_t)n * D;
        a0 += row[tid]       * m;
        a1 += row[tid + 256] * m;
        a2 += row[tid + 512] * m;
    }
    float* fr = g_frame_repr + (size_t)bt * D;
    fr[tid]       = a0 / den;
    fr[tid + 256] = a1 / den;
    fr[tid + 512] = a2 / den;
}

// ================= K2: EMA novelty seed + frame FPS (per batch) =================
__global__ void novelty_fps_kernel() {
    int b = blockIdx.x;
    int tid = threadIdx.x;
    int lane = tid & 31, w = tid >> 5;
    const float* R = g_frame_repr + (size_t)b * T * D;

    __shared__ float s_nov[T];
    __shared__ float s_part[8];
    __shared__ float s_ref[D];
    __shared__ float s_md[T];
    __shared__ float s_rv[8];
    __shared__ int   s_ri[8];
    __shared__ int   s_res;

    // EMA novelty (sequential over T); each thread owns 3 dims of ema
    float e0 = R[tid], e1 = R[tid + 256], e2 = R[tid + 512];
    for (int t = 0; t < T; t++) {
        float f0 = R[(size_t)t * D + tid];
        float f1 = R[(size_t)t * D + tid + 256];
        float f2 = R[(size_t)t * D + tid + 512];
        float d0 = f0 - e0, d1 = f1 - e1, d2 = f2 - e2;
        float sq = d0 * d0 + d1 * d1 + d2 * d2;
#pragma unroll
        for (int o = 16; o; o >>= 1) sq += __shfl_down_sync(0xffffffffu, sq, o);
        if (lane == 0) s_part[w] = sq;
        __syncthreads();
        if (tid == 0) {
            float s = 0.f;
            for (int i = 0; i < 8; i++) s += s_part[i];
            s_nov[t] = s;
        }
        e0 = 0.9f * e0 + 0.1f * f0;
        e1 = 0.9f * e1 + 0.1f * f1;
        e2 = 0.9f * e2 + 0.1f * f2;
        __syncthreads();
    }

    // seed = argmax novelty
    float v = (tid < T) ? s_nov[tid] : -1.f;
    int last = block_argmax_256(v, tid, s_rv, s_ri, &s_res);
    if (tid == 0) g_frame_idx[b * KF] = last;

    if (tid < T) s_md[tid] = __int_as_float(0x7f800000);  // +inf

    for (int step = 1; step < KF; step++) {
        // broadcast reference row
        s_ref[tid]       = R[(size_t)last * D + tid];
        s_ref[tid + 256] = R[(size_t)last * D + tid + 256];
        s_ref[tid + 512] = R[(size_t)last * D + tid + 512];
        __syncthreads();
        // each warp handles 16 rows
#pragma unroll 1
        for (int j = 0; j < 16; j++) {
            int r = w * 16 + j;
            const float* row = R + (size_t)r * D;
            float acc = 0.f;
#pragma unroll
            for (int q = 0; q < 24; q++) {
                float dd = row[lane + 32 * q] - s_ref[lane + 32 * q];
                acc += dd * dd;
            }
#pragma unroll
            for (int o = 16; o; o >>= 1) acc += __shfl_down_sync(0xffffffffu, acc, o);
            if (lane == 0) s_md[r] = fminf(s_md[r], acc);
        }
        __syncthreads();
        if (tid == 0) s_md[last] = -1.f;
        __syncthreads();
        float mv = (tid < T) ? s_md[tid] : -2.f;
        last = block_argmax_256(mv, tid, s_rv, s_ri, &s_res);
        if (tid == 0) g_frame_idx[b * KF + step] = last;
    }
}

// ================= K3: Gram matrices for selected frames =================
// grid (2,2,64): 98x98 quadrant of 196x196 per block, K=768 in chunks of 16.
// 224 threads; 196 active compute threads with 7x7 register tiles; f32x2 FMAs.
#define KC  16
#define LDA 18

__global__ __launch_bounds__(224, 1) void gram_kernel(const float* __restrict__ x) {
    int f = blockIdx.z;
    int b = f >> 4;
    int fidx = g_frame_idx[f];
    const float* F = x + ((size_t)(b * T + fidx)) * NTOK * D;
    int qi = blockIdx.x, qj = blockIdx.y;
    int tid = threadIdx.x;

    __shared__ float As[2][98 * LDA];
    __shared__ float Bs[2][98 * LDA];

    int lrow[7], lcol[7];
#pragma unroll
    for (int r = 0; r < 7; r++) {
        int idx = tid + 224 * r;       // < 1568 = 98*16
        lrow[r] = idx >> 4;
        lcol[r] = idx & 15;
    }

    float ra[7], rb[7];

    unsigned long long acc[49];
#pragma unroll
    for (int i = 0; i < 49; i++) acc[i] = 0ull;

    int ti = tid % 14, tj = tid / 14;
    bool active = tid < 196;

    // prologue: load chunk 0
#pragma unroll
    for (int r = 0; r < 7; r++) {
        ra[r] = F[(size_t)(qi * 98 + lrow[r]) * D + lcol[r]];
        rb[r] = F[(size_t)(qj * 98 + lrow[r]) * D + lcol[r]];
    }
#pragma unroll
    for (int r = 0; r < 7; r++) {
        As[0][lrow[r] * LDA + lcol[r]] = ra[r];
        Bs[0][lrow[r] * LDA + lcol[r]] = rb[r];
    }
    __syncthreads();

    const int NCHUNK = D / KC;  // 48
    for (int c = 0; c < NCHUNK; c++) {
        int buf = c & 1;
        if (c + 1 < NCHUNK) {
            int k0 = (c + 1) * KC;
#pragma unroll
            for (int r = 0; r < 7; r++) {
                ra[r] = F[(size_t)(qi * 98 + lrow[r]) * D + k0 + lcol[r]];
                rb[r] = F[(size_t)(qj * 98 + lrow[r]) * D + k0 + lcol[r]];
            }
        }
        if (active) {
            const float* ap = &As[buf][(ti * 7) * LDA];
            const float* bp = &Bs[buf][(tj * 7) * LDA];
#pragma unroll
            for (int kk = 0; kk < KC; kk += 2) {
                unsigned long long a2[7], b2[7];
#pragma unroll
                for (int u = 0; u < 7; u++)
                    a2[u] = *(const unsigned long long*)(ap + u * LDA + kk);
#pragma unroll
                for (int vv = 0; vv < 7; vv++)
                    b2[vv] = *(const unsigned long long*)(bp + vv * LDA + kk);
#pragma unroll
                for (int u = 0; u < 7; u++)
#pragma unroll
                    for (int vv = 0; vv < 7; vv++)
                        asm("fma.rn.f32x2 %0, %1, %2, %0;"
                            : "+l"(acc[u * 7 + vv]) : "l"(a2[u]), "l"(b2[vv]));
            }
        }
        if (c + 1 < NCHUNK) {
            int nb = buf ^ 1;
#pragma unroll
            for (int r = 0; r < 7; r++) {
                As[nb][lrow[r] * LDA + lcol[r]] = ra[r];
                Bs[nb][lrow[r] * LDA + lcol[r]] = rb[r];
            }
        }
        __syncthreads();
    }

    if (active) {
        float* Gp = g_G + (size_t)f * NTOK * NTOK;
#pragma unroll
        for (int u = 0; u < 7; u++) {
            int gi = qi * 98 + ti * 7 + u;
#pragma unroll
            for (int vv = 0; vv < 7; vv++) {
                int gj = qj * 98 + tj * 7 + vv;
                unsigned long long a = acc[u * 7 + vv];
                float lo = __uint_as_float((unsigned int)(a & 0xffffffffull));
                float hi = __uint_as_float((unsigned int)(a >> 32));
                Gp[(size_t)gi * NTOK + gj] = lo + hi;
            }
        }
    }
}

// ================= K4: token FPS from Gram (per selected frame) =================
__global__ void token_fps_kernel() {
    extern __shared__ float Gs[];  // NTOK*NTOK floats
    __shared__ float s_rv[8];
    __shared__ int   s_ri[8];
    __shared__ int   s_res;
    __shared__ int   s_pick[KT];

    int f = blockIdx.x, tid = threadIdx.x;
    const float* Gp = g_G + (size_t)f * NTOK * NTOK;
    for (int i = tid; i < NTOK * NTOK; i += 256) Gs[i] = Gp[i];
    __syncthreads();

    bool act = tid < NTOK;
    float n_i = 0.f, md = -2.f, rs = 0.f;
    if (act) {
        n_i = Gs[tid * NTOK + tid];
        const float* row = Gs + (size_t)tid * NTOK;
        float r0 = 0.f, r1 = 0.f, r2 = 0.f, r3 = 0.f;
        for (int j = 0; j < NTOK; j += 4) {
            r0 += row[j]; r1 += row[j + 1]; r2 += row[j + 2]; r3 += row[j + 3];
        }
        rs = (r0 + r1) + (r2 + r3);
        md = __int_as_float(0x7f800000);  // +inf
    }
    // seed = argmax ||F_i - mu||^2 (up to constant): n_i - (2/196)*rowsum_i
    float sv = act ? (n_i - rs * (2.0f / 196.0f)) : -1e30f;
    int last = block_argmax_256(sv, tid, s_rv, s_ri, &s_res);
    if (tid == 0) s_pick[0] = last;

    for (int s = 1; s < KT; s++) {
        float nlast = Gs[(size_t)last * NTOK + last];  // broadcast
        if (act) {
            float d = n_i + nlast - 2.f * Gs[(size_t)tid * NTOK + last];
            md = fminf(md, d);
            if (tid == last) md = -1.f;
        }
        float mv = act ? md : -2.f;
        last = block_argmax_256(mv, tid, s_rv, s_ri, &s_res);
        if (tid == 0) s_pick[s] = last;
    }
    __syncthreads();
    if (tid < KT) g_token_idx[f * KT + tid] = s_pick[tid];
}

// ================= K5: gather z =================
__global__ void gather_kernel(const float* __restrict__ x, float* __restrict__ out) {
    int row = blockIdx.x;            // 0..3135  (b,k,t2)
    int bk = row / KT;
    int t2 = row - bk * KT;
    int b = bk >> 4;
    int fidx = g_frame_idx[bk];
    int tok = g_token_idx[bk * KT + t2];
    const float4* src = (const float4*)(x + (((size_t)(b * T + fidx)) * NTOK + tok) * D);
    float4* dst = (float4*)(out + (size_t)row * D);
    dst[threadIdx.x] = src[threadIdx.x];
}

// ================= K6: zero mask regions =================
__global__ void zero_kernel(float* __restrict__ out) {
    size_t i = FMASK_OFF + (size_t)blockIdx.x * 256 + threadIdx.x;
    if (i < TOTAL_OUT) out[i] = 0.f;
}

// ================= K7: scatter indices + mask ones =================
__global__ void scatter_kernel(float* __restrict__ out) {
    int gid = blockIdx.x * 256 + threadIdx.x;
    if (gid < B * KF) {
        int fi = g_frame_idx[gid];
        out[FIDX_OFF + gid] = (float)fi;
        out[FMASK_OFF + (size_t)(gid >> 4) * T + fi] = 1.0f;
    }
    if (gid < NF * KT) {
        int bk = gid / KT;
        int b = bk >> 4;
        int fi = g_frame_idx[bk];
        int tk = g_token_idx[gid];
        out[TIDX_OFF + gid] = (float)tk;
        out[TMASK_OFF + ((size_t)(b * T + fi)) * NTOK + tk] = 1.0f;
    }
}

extern "C" void kernel_launch(void* const* d_in, const int* in_sizes, int n_in,
                              void* d_out, int out_size) {
    const float* x    = (const float*)d_in[0];
    const float* mask = (const float*)d_in[1];
    float* out = (float*)d_out;

    frame_repr_kernel<<<B * T, 256>>>(x, mask);
    novelty_fps_kernel<<<B, 256>>>();
    gram_kernel<<<dim3(2, 2, NF), 224>>>(x);

    size_t dyn = (size_t)NTOK * NTOK * sizeof(float);  // 153,664 B
    cudaFuncSetAttribute(token_fps_kernel,
                         cudaFuncAttributeMaxDynamicSharedMemorySize, (int)dyn);
    token_fps_kernel<<<NF, 256, dyn>>>();

    gather_kernel<<<B * KF * KT, 192>>>(x, out);
    zero_kernel<<<(int)((B * T + (size_t)B * T * NTOK + 255) / 256), 256>>>(out);
    scatter_kernel<<<13, 256>>>(out);
}

// round 2
// speedup vs baseline: 2.1461x; 2.1461x over previous
#include <cuda_runtime.h>
#include <math.h>

#define B 4
#define T 128
#define NTOK 196
#define D 768
#define KF 16
#define KT 49
#define NF (B*KF)   // 64 selected frames

// ---- output layout (float32, concatenated flat) ----
#define Z_N       (B*KF*KT*D)                 // 2,408,448
#define FIDX_OFF  ((size_t)Z_N)               // 64 entries
#define TIDX_OFF  (FIDX_OFF + B*KF)           // 3136 entries
#define FMASK_OFF (TIDX_OFF + NF*KT)          // 512 entries
#define TMASK_OFF (FMASK_OFF + B*T)           // 100,352 entries
#define TOTAL_OUT (TMASK_OFF + (size_t)B*T*NTOK)  // 2,512,512

typedef unsigned long long ull;

// ---- device scratch ----
__device__ float g_frame_repr[B*T*D];                 // 1.5 MB
__device__ int   g_frame_idx[NF];
__device__ int   g_token_idx[NF*KT];
__device__ float g_GFp[8][B*128*128];                 // 2 MB   (frame-gram partials)
__device__ float g_Gp[2][(size_t)NF*NTOK*NTOK];       // 19.7MB (token-gram partials)

// ---- warp argmax: strict-greater wins, ties -> lowest index; broadcasts result ----
__device__ __forceinline__ void warp_argmax(float& v, int& ix) {
#pragma unroll
    for (int o = 16; o; o >>= 1) {
        float ov = __shfl_down_sync(0xffffffffu, v, o);
        int   oi = __shfl_down_sync(0xffffffffu, ix, o);
        if (ov > v || (ov == v && oi < ix)) { v = ov; ix = oi; }
    }
    v  = __shfl_sync(0xffffffffu, v, 0);
    ix = __shfl_sync(0xffffffffu, ix, 0);
}

// ================= K0a/K0b: zero the mask regions of out =================
__global__ void zero_fmask_kernel(float* __restrict__ out) {
    int i = blockIdx.x * 256 + threadIdx.x;
    if (i < B * T) out[FMASK_OFF + i] = 0.f;
}
__global__ void zero_tmask_kernel(float* __restrict__ out) {
    int i = blockIdx.x * 256 + threadIdx.x;
    if (i < B * T * NTOK) out[TMASK_OFF + i] = 0.f;
}

// ================= K1: masked-mean frame representation =================
// 192 threads, each owns one float4 of the 768-dim row.
__global__ void frame_repr_kernel(const float* __restrict__ x,
                                  const float* __restrict__ mask) {
    int bt = blockIdx.x;
    const float4* xp4 = (const float4*)(x + (size_t)bt * NTOK * D);
    const float* mp = mask + (size_t)bt * NTOK;
    __shared__ float sm[NTOK];
    __shared__ float s_den;
    int tid = threadIdx.x;
    for (int i = tid; i < NTOK; i += 192) sm[i] = mp[i];
    __syncthreads();
    if (tid == 0) {
        float s = 0.f;
        for (int n = 0; n < NTOK; n++) s += sm[n];
        s_den = fmaxf(s, 1e-6f);
    }
    __syncthreads();
    float inv = 1.0f / s_den;
    float ax = 0.f, ay = 0.f, az = 0.f, aw = 0.f;
#pragma unroll 4
    for (int n = 0; n < NTOK; n++) {
        float m = sm[n];
        float4 v = xp4[n * 192 + tid];
        ax += v.x * m; ay += v.y * m; az += v.z * m; aw += v.w * m;
    }
    float4* fr = (float4*)(g_frame_repr + (size_t)bt * D);
    fr[tid] = make_float4(ax * inv, ay * inv, az * inv, aw * inv);
}

// ================= K2: frame-gram partials GF = R*R^T (per batch, 8-way k-split) =================
// grid (8, B), 256 threads; 128x128 output tile, per-thread 8x8 (strided rows ti+16u).
__global__ __launch_bounds__(256, 1) void gf_partial_kernel() {
    int ks = blockIdx.x, b = blockIdx.y;
    const float* R = g_frame_repr + (size_t)b * T * D;
    __shared__ float As[128 * 18];
    int tid = threadIdx.x;
    int ti = tid & 15, tj = tid >> 4;

    ull acc[64];
#pragma unroll
    for (int i = 0; i < 64; i++) acc[i] = 0ull;

    for (int c = 0; c < 6; c++) {          // 96 dims per block, chunks of 16
        int k0 = ks * 96 + c * 16;
        __syncthreads();
#pragma unroll
        for (int r = 0; r < 8; r++) {
            int idx = tid + 256 * r;       // 2048 = 128*16
            int row = idx >> 4, col = idx & 15;
            As[row * 18 + col] = R[(size_t)row * D + k0 + col];
        }
        __syncthreads();
#pragma unroll
        for (int kk = 0; kk < 16; kk += 2) {
            ull a2[8], b2[8];
#pragma unroll
            for (int u = 0; u < 8; u++)
                a2[u] = *(const ull*)&As[(ti + 16 * u) * 18 + kk];
#pragma unroll
            for (int v = 0; v < 8; v++)
                b2[v] = *(const ull*)&As[(tj + 16 * v) * 18 + kk];
#pragma unroll
            for (int u = 0; u < 8; u++)
#pragma unroll
                for (int v = 0; v < 8; v++)
                    asm("fma.rn.f32x2 %0, %1, %2, %0;"
                        : "+l"(acc[u * 8 + v]) : "l"(a2[u]), "l"(b2[v]));
        }
    }
    float* P = g_GFp[ks] + (size_t)b * 128 * 128;
#pragma unroll
    for (int u = 0; u < 8; u++) {
        int gi = ti + 16 * u;
#pragma unroll
        for (int v = 0; v < 8; v++) {
            int gj = tj + 16 * v;
            ull a = acc[u * 8 + v];
            float lo = __uint_as_float((unsigned)(a & 0xffffffffull));
            float hi = __uint_as_float((unsigned)(a >> 32));
            P[gi * 128 + gj] = lo + hi;
        }
    }
}

// ================= K3: novelty + frame FPS (per batch), barrier-free warp phase =================
__global__ void novelty_fps_kernel(float* __restrict__ out) {
    extern __shared__ float s_GF[];        // 128*128 floats = 64KB
    int b = blockIdx.x, tid = threadIdx.x; // 128 threads

    // sum 8 partials in fixed order (deterministic)
    float4* dst4 = (float4*)s_GF;
    for (int i = tid; i < 128 * 128 / 4; i += 128) {
        float4 a = ((const float4*)(g_GFp[0] + (size_t)b * 16384))[i];
#pragma unroll
        for (int p = 1; p < 8; p++) {
            float4 v = ((const float4*)(g_GFp[p] + (size_t)b * 16384))[i];
            a.x += v.x; a.y += v.y; a.z += v.z; a.w += v.w;
        }
        dst4[i] = a;
    }
    __syncthreads();
    if (tid >= 32) return;
    int lane = tid;

    // EMA novelty via recurrences on c_i = e.f_i, s = |e|^2
    float c[4];
#pragma unroll
    for (int r = 0; r < 4; r++) c[r] = s_GF[lane + 32 * r];  // e = f0
    float s = s_GF[0];
    float bestv = -3e38f; int besti = 0;
#pragma unroll
    for (int t = 0; t < T; t++) {
        int r = t >> 5, t2 = t & 31;
        float ct = __shfl_sync(0xffffffffu, c[r], t2);
        float gtt = s_GF[t * 128 + t];
        float nv = gtt - 2.f * ct + s;
        if (nv > bestv) { bestv = nv; besti = t; }
#pragma unroll
        for (int rr = 0; rr < 4; rr++)
            c[rr] = 0.9f * c[rr] + 0.1f * s_GF[t * 128 + lane + 32 * rr];
        s = 0.81f * s + 0.18f * ct + 0.01f * gtt;
    }

    int last = besti;
    if (lane == 0) {
        g_frame_idx[b * KF] = last;
        out[FIDX_OFF + b * KF] = (float)last;
        out[FMASK_OFF + b * T + last] = 1.0f;
    }

    float n[4], md[4];
#pragma unroll
    for (int r = 0; r < 4; r++) {
        int i = lane + 32 * r;
        n[r] = s_GF[i * 128 + i];
        md[r] = __int_as_float(0x7f800000);
    }
    for (int step = 1; step < KF; step++) {
        float nl = s_GF[last * 128 + last];
        float bv = -3e38f; int bi = 0x7fffffff;
#pragma unroll
        for (int r = 0; r < 4; r++) {
            int i = lane + 32 * r;
            float d = n[r] + nl - 2.f * s_GF[last * 128 + i];
            md[r] = fminf(md[r], d);
            if (i == last) md[r] = -1.f;
            if (md[r] > bv) { bv = md[r]; bi = i; }
        }
        warp_argmax(bv, bi);
        last = bi;
        if (lane == 0) {
            g_frame_idx[b * KF + step] = last;
            out[FIDX_OFF + b * KF + step] = (float)last;
            out[FMASK_OFF + b * T + last] = 1.0f;
        }
    }
}

// ================= K4: token-gram partials for selected frames =================
// grid (3 quad-pairs, 2 k-halves, 64 frames), 224 threads, 98x98 tile, 7x7/thread.
#define KC  16
#define LDA 18

__global__ __launch_bounds__(224, 1) void gram_kernel(const float* __restrict__ x) {
    int qp = blockIdx.x;                     // 0:(0,0) 1:(0,1) 2:(1,1)
    int h  = blockIdx.y;                     // k half
    int f  = blockIdx.z;
    int qi = qp >> 1, qj = (qp + 1) >> 1;
    int b = f >> 4;
    int fidx = g_frame_idx[f];
    const float* F = x + ((size_t)(b * T + fidx)) * NTOK * D;
    int tid = threadIdx.x;

    __shared__ float As[2][98 * LDA];
    __shared__ float Bs[2][98 * LDA];

    int lrow[7], lcol[7];
#pragma unroll
    for (int r = 0; r < 7; r++) {
        int idx = tid + 224 * r;             // < 1568 = 98*16
        lrow[r] = idx >> 4;
        lcol[r] = idx & 15;
    }

    float ra[7], rb[7];
    ull acc[49];
#pragma unroll
    for (int i = 0; i < 49; i++) acc[i] = 0ull;

    int ti = tid % 14, tj = tid / 14;
    bool active = tid < 196;
    int kbase = h * 384;

#pragma unroll
    for (int r = 0; r < 7; r++) {
        ra[r] = F[(size_t)(qi * 98 + lrow[r]) * D + kbase + lcol[r]];
        rb[r] = F[(size_t)(qj * 98 + lrow[r]) * D + kbase + lcol[r]];
    }
#pragma unroll
    for (int r = 0; r < 7; r++) {
        As[0][lrow[r] * LDA + lcol[r]] = ra[r];
        Bs[0][lrow[r] * LDA + lcol[r]] = rb[r];
    }
    __syncthreads();

    const int NCH = 384 / KC;                // 24
    for (int c = 0; c < NCH; c++) {
        int buf = c & 1;
        if (c + 1 < NCH) {
            int k0 = kbase + (c + 1) * KC;
#pragma unroll
            for (int r = 0; r < 7; r++) {
                ra[r] = F[(size_t)(qi * 98 + lrow[r]) * D + k0 + lcol[r]];
                rb[r] = F[(size_t)(qj * 98 + lrow[r]) * D + k0 + lcol[r]];
            }
        }
        if (active) {
            const float* ap = &As[buf][(ti * 7) * LDA];
            const float* bp = &Bs[buf][(tj * 7) * LDA];
#pragma unroll
            for (int kk = 0; kk < KC; kk += 2) {
                ull a2[7], b2[7];
#pragma unroll
                for (int u = 0; u < 7; u++)
                    a2[u] = *(const ull*)(ap + u * LDA + kk);
#pragma unroll
                for (int vv = 0; vv < 7; vv++)
                    b2[vv] = *(const ull*)(bp + vv * LDA + kk);
#pragma unroll
                for (int u = 0; u < 7; u++)
#pragma unroll
                    for (int vv = 0; vv < 7; vv++)
                        asm("fma.rn.f32x2 %0, %1, %2, %0;"
                            : "+l"(acc[u * 7 + vv]) : "l"(a2[u]), "l"(b2[vv]));
            }
        }
        if (c + 1 < NCH) {
            int nb = buf ^ 1;
#pragma unroll
            for (int r = 0; r < 7; r++) {
                As[nb][lrow[r] * LDA + lcol[r]] = ra[r];
                Bs[nb][lrow[r] * LDA + lcol[r]] = rb[r];
            }
        }
        __syncthreads();
    }

    if (active) {
        float* Gp = g_Gp[h] + (size_t)f * NTOK * NTOK;
#pragma unroll
        for (int u = 0; u < 7; u++) {
            int gi = qi * 98 + ti * 7 + u;
#pragma unroll
            for (int vv = 0; vv < 7; vv++) {
                int gj = qj * 98 + tj * 7 + vv;
                ull a = acc[u * 7 + vv];
                float lo = __uint_as_float((unsigned)(a & 0xffffffffull));
                float hi = __uint_as_float((unsigned)(a >> 32));
                float v = lo + hi;
                Gp[(size_t)gi * NTOK + gj] = v;
                if (qp == 1) Gp[(size_t)gj * NTOK + gi] = v;
            }
        }
    }
}

// ================= K5: token FPS (per selected frame), barrier-free warp phase =================
#define GPAD 197
__global__ void token_fps_kernel(float* __restrict__ out) {
    extern __shared__ float Gs[];            // NTOK*GPAD floats
    __shared__ float s_rs[NTOK];

    int f = blockIdx.x, tid = threadIdx.x;   // 224 threads
    const float* p0 = g_Gp[0] + (size_t)f * NTOK * NTOK;
    const float* p1 = g_Gp[1] + (size_t)f * NTOK * NTOK;
    // sum two k-halves in fixed order (deterministic)
    if (tid < NTOK) {
        for (int i = 0; i < NTOK; i++)
            Gs[i * GPAD + tid] = p0[i * NTOK + tid] + p1[i * NTOK + tid];
    }
    __syncthreads();
    // row sums (for the farthest-from-mean seed)
    if (tid < NTOK) {
        const float* row = &Gs[tid * GPAD];
        float r0 = 0.f, r1 = 0.f, r2 = 0.f, r3 = 0.f;
#pragma unroll 4
        for (int j = 0; j < NTOK; j += 4) {
            r0 += row[j]; r1 += row[j + 1]; r2 += row[j + 2]; r3 += row[j + 3];
        }
        s_rs[tid] = (r0 + r1) + (r2 + r3);
    }
    __syncthreads();
    if (tid >= 32) return;
    int lane = tid;
    int fidx = g_frame_idx[f];
    int bb = f >> 4;
    size_t tmask_base = TMASK_OFF + ((size_t)(bb * T + fidx)) * NTOK;

    float n[7], md[7];
    float bv = -3e38f; int bi = 0x7fffffff;
#pragma unroll
    for (int q = 0; q < 7; q++) {
        int i = lane + 32 * q;
        bool val = i < NTOK;
        n[q]  = val ? Gs[i * GPAD + i] : 0.f;
        md[q] = val ? __int_as_float(0x7f800000) : -3e38f;
        float v = val ? (n[q] - s_rs[i] * (2.0f / 196.0f)) : -3e38f;
        if (v > bv) { bv = v; bi = i; }
    }
    warp_argmax(bv, bi);
    int last = bi;
    if (lane == 0) {
        g_token_idx[f * KT] = last;
        out[TIDX_OFF + f * KT] = (float)last;
        out[tmask_base + last] = 1.0f;
    }

    for (int s = 1; s < KT; s++) {
        float nl = Gs[last * GPAD + last];
        bv = -3e38f; bi = 0x7fffffff;
#pragma unroll
        for (int q = 0; q < 7; q++) {
            int i = lane + 32 * q;
            bool val = i < NTOK;
            float g = val ? Gs[last * GPAD + i] : 0.f;
            float d = n[q] + nl - 2.f * g;
            md[q] = fminf(md[q], d);
            if (i == last) md[q] = -1.f;
            float mv = val ? md[q] : -3e38f;
            if (mv > bv) { bv = mv; bi = i; }
        }
        warp_argmax(bv, bi);
        last = bi;
        if (lane == 0) {
            g_token_idx[f * KT + s] = last;
            out[TIDX_OFF + f * KT + s] = (float)last;
            out[tmask_base + last] = 1.0f;
        }
    }
}

// ================= K6: gather z =================
__global__ void gather_kernel(const float* __restrict__ x, float* __restrict__ out) {
    int row = blockIdx.x;                    // 0..3135
    int bk = row / KT;
    int t2 = row - bk * KT;
    int b = bk >> 4;
    int fidx = g_frame_idx[bk];
    int tok = g_token_idx[bk * KT + t2];
    const float4* src = (const float4*)(x + (((size_t)(b * T + fidx)) * NTOK + tok) * D);
    float4* dst = (float4*)(out + (size_t)row * D);
    dst[threadIdx.x] = src[threadIdx.x];
}

extern "C" void kernel_launch(void* const* d_in, const int* in_sizes, int n_in,
                              void* d_out, int out_size) {
    const float* x    = (const float*)d_in[0];
    const float* mask = (const float*)d_in[1];
    float* out = (float*)d_out;

    zero_fmask_kernel<<<2, 256>>>(out);                        // launch 1
    zero_tmask_kernel<<<(B * T * NTOK + 255) / 256, 256>>>(out);  // launch 2
    frame_repr_kernel<<<B * T, 192>>>(x, mask);                // launch 3
    gf_partial_kernel<<<dim3(8, B), 256>>>();                  // launch 4

    cudaFuncSetAttribute(novelty_fps_kernel,
                         cudaFuncAttributeMaxDynamicSharedMemorySize, 128 * 128 * 4);
    novelty_fps_kernel<<<B, 128, 128 * 128 * 4>>>(out);        // launch 5

    gram_kernel<<<dim3(3, 2, NF), 224>>>(x);                   // launch 6 (ncu capture)

    size_t dyn = (size_t)NTOK * GPAD * sizeof(float);          // 154,448 B
    cudaFuncSetAttribute(token_fps_kernel,
                         cudaFuncAttributeMaxDynamicSharedMemorySize, (int)dyn);
    token_fps_kernel<<<NF, 224, dyn>>>(out);                   // launch 7

    gather_kernel<<<B * KF * KT, 192>>>(x, out);               // launch 8
}